// round 13
// baseline (speedup 1.0000x reference)
#include <cuda_runtime.h>
#include <cuda_bf16.h>
#include <stdint.h>

#define NB_B     128      // batch rows
#define NB_DIM   1024     // latent dim
#define NB_BINS  16384    // histogram bins / num_outputs
#define NB_MULT  128      // multiplier

// Bit-exact replica of XLA CPU's vectorized f32 exp (GenerateVF32Exp,
// Cephes polynomial).  DO NOT MODIFY — bit-exactness verified R9.
__device__ __forceinline__ float xla_expf(float input) {
    float x = fminf(fmaxf(input, -88.3762626647949f), 88.3762626647950f);
    float fx = floorf(fmaf(x, 1.44269504088896341f, 0.5f));
    float tmp = __fmul_rn(fx, 0.693359375f);
    float zz  = __fmul_rn(fx, -2.12194440e-4f);
    x = __fsub_rn(x, tmp);
    x = __fsub_rn(x, zz);
    zz = __fmul_rn(x, x);
    float y = fmaf(x, 1.9875691500E-4f, 1.3981999507E-3f);
    y = fmaf(y, x, 8.3334519073E-3f);
    y = fmaf(y, x, 4.1665795894E-2f);
    y = fmaf(y, x, 1.6666665459E-1f);
    y = fmaf(y, x, 5.0000001201E-1f);
    y = fmaf(y, zz, x);
    y = __fadd_rn(1.0f, y);
    int emm0 = ((int)fx + 127) << 23;
    float two_n = __int_as_float(emm0);
    return fmaxf(__fmul_rn(y, two_n), input);
}

// ---------------- Fused kernel: one CTA per batch row ----------------
// Phase A: stream row slice (512KB) tracking RAW-eps column min/max only
//          (z min/max derived exactly afterwards via monotonicity:
//          z = rnd(sm + rnd(ss*e)) with ss>0 is monotone in e under RN).
// Phase B: re-stream slice (L2-resident), smem-atomic histogram.
// Tail:    single-pass online softmax over integer counts (exp LUT).
__global__ __launch_bounds__(1024) void k_fused(const float* __restrict__ zm,
                                                const float* __restrict__ zv,
                                                const float* __restrict__ eps,
                                                const float* __restrict__ x,
                                                float* __restrict__ out) {
    extern __shared__ unsigned smem[];
    unsigned* hist = smem;                          // NB_BINS u32 (64KB)
    // Phase-A staging (overlaps hist area; consumed before hist is zeroed):
    float4* scmin4 = (float4*)smem;                 // [4][256] float4
    float4* scmax4 = scmin4 + 1024;                 // [4][256] float4
    float* scmin = (float*)scmin4;                  // [4][1024]
    float* scmax = (float*)scmax4;                  // [4][1024]
    float* s_s  = (float*)(smem + NB_BINS);         // NB_DIM
    float* s_zm = s_s + NB_DIM;                     // NB_DIM
    __shared__ float s_rmin[32], s_rmax[32], s_red[32];
    __shared__ int   s_mred[32];
    __shared__ float s_bcast[4];
    __shared__ float s_lut[256];                    // expf(-d), d=0..255

    const int b = blockIdx.x;
    const int t = threadIdx.x;
    const int wid = t >> 5, lane = t & 31;

    // ---- prefetch x row (consumed only in epilogue; hides under phase A) ----
    float xv[NB_BINS / 1024];
    {
        const float* xrow = x + (size_t)b * NB_BINS;
        #pragma unroll
        for (int i = 0; i < NB_BINS / 1024; ++i) xv[i] = __ldg(&xrow[t + i * 1024]);
    }

    // exp LUT: expf(-(float)dd) — bit-identical to softmax expf on int args.
    // expf(x)==0 exactly for x <= -104, so dd>=256 -> 0.
    if (t < 256) s_lut[t] = expf(-(float)t);

    // Cache z_mean row and stdev row.  0.5*zv is exact (power of 2).
    s_zm[t] = zm[b * NB_DIM + t];
    s_s[t]  = xla_expf(__fmul_rn(0.5f, zv[b * NB_DIM + t]));

    const int jrow = t >> 8;      // 0..3
    const int d4   = t & 255;     // 0..255

    const float* __restrict__ row_base = eps + (size_t)b * NB_MULT * NB_DIM;

    // ---------------- Phase A: raw-eps column min/max ----------------
    float m0 =  3.402823466e38f, m1 = m0, m2 = m0, m3 = m0;
    float M0 = -3.402823466e38f, M1 = M0, M2 = M0, M3 = M0;

    #pragma unroll 8
    for (int it = 0; it < 32; ++it) {
        int j = it * 4 + jrow;
        const float4* ep = reinterpret_cast<const float4*>(row_base + (size_t)j * NB_DIM);
        float4 e = ep[d4];
        m0 = fminf(m0, e.x); M0 = fmaxf(M0, e.x);
        m1 = fminf(m1, e.y); M1 = fmaxf(M1, e.y);
        m2 = fminf(m2, e.z); M2 = fmaxf(M2, e.z);
        m3 = fminf(m3, e.w); M3 = fmaxf(M3, e.w);
    }
    scmin4[jrow * 256 + d4] = make_float4(m0, m1, m2, m3);
    scmax4[jrow * 256 + d4] = make_float4(M0, M1, M2, M3);
    __syncthreads();   // staging + s_zm/s_s visible

    // Derive per-column z-extrema (exact by monotonicity: ss>0), then reduce.
    {
        float cmin = fminf(fminf(scmin[t], scmin[1024 + t]),
                           fminf(scmin[2048 + t], scmin[3072 + t]));
        float cmax = fmaxf(fmaxf(scmax[t], scmax[1024 + t]),
                           fmaxf(scmax[2048 + t], scmax[3072 + t]));
        // z = zm + s*eps, NON-contracted (plain fmul/fadd). DO NOT fuse.
        float lo = __fadd_rn(s_zm[t], __fmul_rn(s_s[t], cmin));
        float hi = __fadd_rn(s_zm[t], __fmul_rn(s_s[t], cmax));
        #pragma unroll
        for (int o = 16; o; o >>= 1) {
            lo = fminf(lo, __shfl_down_sync(0xffffffffu, lo, o));
            hi = fmaxf(hi, __shfl_down_sync(0xffffffffu, hi, o));
        }
        if (lane == 0) { s_rmin[wid] = lo; s_rmax[wid] = hi; }
    }
    __syncthreads();   // s_rmin/s_rmax ready; staging fully consumed
    if (wid == 0) {
        float lo = s_rmin[lane], hi = s_rmax[lane];
        #pragma unroll
        for (int o = 16; o; o >>= 1) {
            lo = fminf(lo, __shfl_down_sync(0xffffffffu, lo, o));
            hi = fmaxf(hi, __shfl_down_sync(0xffffffffu, hi, o));
        }
        if (lane == 0) { s_bcast[0] = lo; s_bcast[1] = hi; }
    }
    // zero histogram (overwrites staging — consumed above) while warp0 reduces
    #pragma unroll
    for (int i = 0; i < NB_BINS / 1024; ++i) hist[t + i * 1024] = 0u;
    __syncthreads();

    const float mn = s_bcast[0];
    const float dr = __fsub_rn(s_bcast[1], mn);
    // Fast-math reciprocal fold: scaled = (z-mn) * c2, c2 = (1/dr)*16384
    // (*2^14 exact; rnd(16384/dr) == rnd(1/dr)*2^14 bitwise). DO NOT change.
    const float c2 = __fmul_rn(__fdiv_rn(1.0f, dr), 16384.0f);

    const int d = d4 * 4;
    const float sm0 = s_zm[d], sm1 = s_zm[d+1], sm2 = s_zm[d+2], sm3 = s_zm[d+3];
    const float ss0 = s_s[d],  ss1 = s_s[d+1],  ss2 = s_s[d+2],  ss3 = s_s[d+3];

    // ---------------- Phase B: histogram (L2-hot re-read) ----------------
    #pragma unroll 8
    for (int it = 0; it < 32; ++it) {
        int j = it * 4 + jrow;
        const float4* ep = reinterpret_cast<const float4*>(row_base + (size_t)j * NB_DIM);
        float4 e = ep[d4];
        float z0 = __fadd_rn(sm0, __fmul_rn(ss0, e.x));
        float z1 = __fadd_rn(sm1, __fmul_rn(ss1, e.y));
        float z2 = __fadd_rn(sm2, __fmul_rn(ss2, e.z));
        float z3 = __fadd_rn(sm3, __fmul_rn(ss3, e.w));
        float c0 = __fmul_rn(__fsub_rn(z0, mn), c2);
        float c1 = __fmul_rn(__fsub_rn(z1, mn), c2);
        float cc = __fmul_rn(__fsub_rn(z2, mn), c2);
        float c3 = __fmul_rn(__fsub_rn(z3, mn), c2);
        int i0 = min(max((int)c0, 0), NB_BINS - 1);
        int i1 = min(max((int)c1, 0), NB_BINS - 1);
        int i2 = min(max((int)cc, 0), NB_BINS - 1);
        int i3 = min(max((int)c3, 0), NB_BINS - 1);
        atomicAdd(&hist[i0], 1u);
        atomicAdd(&hist[i1], 1u);
        atomicAdd(&hist[i2], 1u);
        atomicAdd(&hist[i3], 1u);
    }
    __syncthreads();

    // ---------------- single-pass online softmax over counts ----------------
    // (m, s): running int max + sum of exp(c - m) via LUT.  Value identical to
    // two-pass up to fp summation order (~1e-7), counts untouched.
    int   mrun = -0x40000000;
    float srun = 0.0f;
    #pragma unroll
    for (int i = 0; i < NB_BINS / 1024; ++i) {
        int c = (int)hist[t + i * 1024];
        if (c > mrun) {
            int dd = c - mrun;
            float g = (dd < 256) ? s_lut[dd] : 0.0f;
            srun = __fadd_rn(__fmul_rn(srun, g), 1.0f);
            mrun = c;
        } else {
            int dd = mrun - c;
            srun = __fadd_rn(srun, (dd < 256) ? s_lut[dd] : 0.0f);
        }
    }
    #pragma unroll
    for (int o = 16; o; o >>= 1) {
        int   m2 = __shfl_down_sync(0xffffffffu, mrun, o);
        float s2 = __shfl_down_sync(0xffffffffu, srun, o);
        if (m2 > mrun) {
            int dd = m2 - mrun;
            float g = (dd < 256) ? s_lut[dd] : 0.0f;
            srun = __fadd_rn(s2, __fmul_rn(srun, g));
            mrun = m2;
        } else {
            int dd = mrun - m2;
            srun = __fadd_rn(srun, __fmul_rn(s2, (dd < 256) ? s_lut[dd] : 0.0f));
        }
    }
    if (lane == 0) { s_mred[wid] = mrun; s_red[wid] = srun; }
    __syncthreads();
    if (wid == 0) {
        mrun = s_mred[lane];
        srun = s_red[lane];
        #pragma unroll
        for (int o = 16; o; o >>= 1) {
            int   m2 = __shfl_down_sync(0xffffffffu, mrun, o);
            float s2 = __shfl_down_sync(0xffffffffu, srun, o);
            if (m2 > mrun) {
                int dd = m2 - mrun;
                float g = (dd < 256) ? s_lut[dd] : 0.0f;
                srun = __fadd_rn(s2, __fmul_rn(srun, g));
                mrun = m2;
            } else {
                int dd = mrun - m2;
                srun = __fadd_rn(srun, __fmul_rn(s2, (dd < 256) ? s_lut[dd] : 0.0f));
            }
        }
        if (lane == 0) { s_bcast[2] = (float)mrun; s_bcast[3] = srun; }
    }
    __syncthreads();
    const int cmaxi = (int)s_bcast[2];
    const float rtot = __fdiv_rn(1.0f, s_bcast[3]);

    // epilogue: probs = exp(c-cmax)/total; prune < 1e-10; out = (x*p)*128
    float* orow = out + (size_t)b * NB_BINS;
    #pragma unroll
    for (int i = 0; i < NB_BINS / 1024; ++i) {
        int n = t + i * 1024;
        int dd = cmaxi - (int)hist[n];
        float ev = (dd < 256) ? s_lut[dd] : 0.0f;
        float p = __fmul_rn(ev, rtot);
        if (p < 1e-10f) p = 0.0f;
        orow[n] = __fmul_rn(__fmul_rn(xv[i], p), 128.0f);
    }
}

extern "C" void kernel_launch(void* const* d_in, const int* in_sizes, int n_in,
                              void* d_out, int out_size) {
    const float* zm  = (const float*)d_in[0];
    const float* zv  = (const float*)d_in[1];
    const float* x   = (const float*)d_in[2];
    const float* eps = (const float*)d_in[3];
    float* out = (float*)d_out;

    const int smem = NB_BINS * 4 + 2 * NB_DIM * 4;  // 73728 B
    cudaFuncSetAttribute(k_fused, cudaFuncAttributeMaxDynamicSharedMemorySize, smem);

    k_fused<<<NB_B, 1024, smem>>>(zm, zv, eps, x, out);
}

// round 14
// speedup vs baseline: 1.5337x; 1.5337x over previous
#include <cuda_runtime.h>
#include <cuda_bf16.h>
#include <stdint.h>

#define NB_B     128      // batch rows
#define NB_DIM   1024     // latent dim
#define NB_BINS  16384    // histogram bins / num_outputs
#define NB_MULT  128      // multiplier

// Bit-exact replica of XLA CPU's vectorized f32 exp (GenerateVF32Exp,
// Cephes polynomial).  DO NOT MODIFY — bit-exactness verified R9.
__device__ __forceinline__ float xla_expf(float input) {
    float x = fminf(fmaxf(input, -88.3762626647949f), 88.3762626647950f);
    float fx = floorf(fmaf(x, 1.44269504088896341f, 0.5f));
    float tmp = __fmul_rn(fx, 0.693359375f);
    float zz  = __fmul_rn(fx, -2.12194440e-4f);
    x = __fsub_rn(x, tmp);
    x = __fsub_rn(x, zz);
    zz = __fmul_rn(x, x);
    float y = fmaf(x, 1.9875691500E-4f, 1.3981999507E-3f);
    y = fmaf(y, x, 8.3334519073E-3f);
    y = fmaf(y, x, 4.1665795894E-2f);
    y = fmaf(y, x, 1.6666665459E-1f);
    y = fmaf(y, x, 5.0000001201E-1f);
    y = fmaf(y, zz, x);
    y = __fadd_rn(1.0f, y);
    int emm0 = ((int)fx + 127) << 23;
    float two_n = __int_as_float(emm0);
    return fmaxf(__fmul_rn(y, two_n), input);
}

// ---------------- Fused kernel: one CTA per batch row (R11 structure) ----
// Phase A: stream row slice (512KB), per-thread RAW-eps extrema for the
//          thread's 4 fixed columns; transform to z-extrema once per column
//          after the loop (exact: z = rnd(sm + rnd(ss*e)), ss>0, RN rounding
//          is monotone), then R11's unchanged warp/block reduction.
// Phase B: re-stream slice (L2-resident), smem-atomic histogram.
// Tail:    two-pass softmax over integer counts via exp LUT (R11 verbatim).
__global__ __launch_bounds__(1024) void k_fused(const float* __restrict__ zm,
                                                const float* __restrict__ zv,
                                                const float* __restrict__ eps,
                                                const float* __restrict__ x,
                                                float* __restrict__ out) {
    extern __shared__ unsigned smem[];
    unsigned* hist = smem;                          // NB_BINS u32 (64KB)
    float* s_s  = (float*)(smem + NB_BINS);         // NB_DIM
    float* s_zm = s_s + NB_DIM;                     // NB_DIM
    __shared__ float s_rmin[32], s_rmax[32], s_red[32];
    __shared__ float s_bcast[4];
    __shared__ float s_lut[256];                    // expf(-d), d=0..255

    const int b = blockIdx.x;
    const int t = threadIdx.x;
    const int wid = t >> 5, lane = t & 31;

    // ---- prefetch x row (consumed only in epilogue; hides under phase A) ----
    float xv[NB_BINS / 1024];
    {
        const float* xrow = x + (size_t)b * NB_BINS;
        #pragma unroll
        for (int i = 0; i < NB_BINS / 1024; ++i) xv[i] = __ldg(&xrow[t + i * 1024]);
    }

    // zero histogram
    #pragma unroll
    for (int i = 0; i < NB_BINS / 1024; ++i) hist[t + i * 1024] = 0u;

    // exp LUT: expf(-(float)d) — bit-identical to the softmax expf calls
    // (integer args). expf(x)==0 exactly for x <= -104, so d>=256 -> 0.
    if (t < 256) s_lut[t] = expf(-(float)t);

    // Cache z_mean row and stdev row.  0.5*zv is exact (power of 2).
    s_zm[t] = zm[b * NB_DIM + t];
    s_s[t]  = xla_expf(__fmul_rn(0.5f, zv[b * NB_DIM + t]));
    __syncthreads();

    const int jrow = t >> 8;      // 0..3
    const int d4   = t & 255;     // 0..255
    const int d    = d4 * 4;

    const float* __restrict__ row_base = eps + (size_t)b * NB_MULT * NB_DIM;

    // ---------------- Phase A: raw-eps per-column extrema ----------------
    float m0 =  3.402823466e38f, m1 = m0, m2 = m0, m3 = m0;
    float M0 = -3.402823466e38f, M1 = M0, M2 = M0, M3 = M0;

    #pragma unroll 4
    for (int it = 0; it < 32; ++it) {
        int j = it * 4 + jrow;
        const float4* ep = reinterpret_cast<const float4*>(row_base + (size_t)j * NB_DIM);
        float4 e = ep[d4];
        m0 = fminf(m0, e.x); M0 = fmaxf(M0, e.x);
        m1 = fminf(m1, e.y); M1 = fmaxf(M1, e.y);
        m2 = fminf(m2, e.z); M2 = fmaxf(M2, e.z);
        m3 = fminf(m3, e.w); M3 = fmaxf(M3, e.w);
    }

    const float sm0 = s_zm[d], sm1 = s_zm[d+1], sm2 = s_zm[d+2], sm3 = s_zm[d+3];
    const float ss0 = s_s[d],  ss1 = s_s[d+1],  ss2 = s_s[d+2],  ss3 = s_s[d+3];

    // Transform raw extrema -> z extrema (exact by monotonicity; ss>0).
    // z = zm + s*eps, NON-contracted (plain fmul/fadd). DO NOT fuse.
    float vmin, vmax;
    {
        float l0 = __fadd_rn(sm0, __fmul_rn(ss0, m0));
        float l1 = __fadd_rn(sm1, __fmul_rn(ss1, m1));
        float l2 = __fadd_rn(sm2, __fmul_rn(ss2, m2));
        float l3 = __fadd_rn(sm3, __fmul_rn(ss3, m3));
        float h0 = __fadd_rn(sm0, __fmul_rn(ss0, M0));
        float h1 = __fadd_rn(sm1, __fmul_rn(ss1, M1));
        float h2 = __fadd_rn(sm2, __fmul_rn(ss2, M2));
        float h3 = __fadd_rn(sm3, __fmul_rn(ss3, M3));
        vmin = fminf(fminf(l0, l1), fminf(l2, l3));
        vmax = fmaxf(fmaxf(h0, h1), fmaxf(h2, h3));
    }

    #pragma unroll
    for (int o = 16; o; o >>= 1) {
        vmin = fminf(vmin, __shfl_down_sync(0xffffffffu, vmin, o));
        vmax = fmaxf(vmax, __shfl_down_sync(0xffffffffu, vmax, o));
    }
    if (lane == 0) { s_rmin[wid] = vmin; s_rmax[wid] = vmax; }
    __syncthreads();
    if (wid == 0) {
        vmin = s_rmin[lane];
        vmax = s_rmax[lane];
        #pragma unroll
        for (int o = 16; o; o >>= 1) {
            vmin = fminf(vmin, __shfl_down_sync(0xffffffffu, vmin, o));
            vmax = fmaxf(vmax, __shfl_down_sync(0xffffffffu, vmax, o));
        }
        if (lane == 0) { s_bcast[0] = vmin; s_bcast[1] = vmax; }
    }
    __syncthreads();

    const float mn = s_bcast[0];
    const float dr = __fsub_rn(s_bcast[1], mn);
    // Fast-math reciprocal fold: scaled = (z-mn) * c2, c2 = (1/dr)*16384
    // (*2^14 exact; rnd(16384/dr) == rnd(1/dr)*2^14 bitwise). DO NOT change.
    const float c2 = __fmul_rn(__fdiv_rn(1.0f, dr), 16384.0f);

    // ---------------- Phase B: histogram (L2-hot re-read) ----------------
    #pragma unroll 8
    for (int it = 0; it < 32; ++it) {
        int j = it * 4 + jrow;
        const float4* ep = reinterpret_cast<const float4*>(row_base + (size_t)j * NB_DIM);
        float4 e = ep[d4];
        float z0 = __fadd_rn(sm0, __fmul_rn(ss0, e.x));
        float z1 = __fadd_rn(sm1, __fmul_rn(ss1, e.y));
        float z2 = __fadd_rn(sm2, __fmul_rn(ss2, e.z));
        float z3 = __fadd_rn(sm3, __fmul_rn(ss3, e.w));
        float c0 = __fmul_rn(__fsub_rn(z0, mn), c2);
        float c1 = __fmul_rn(__fsub_rn(z1, mn), c2);
        float cc = __fmul_rn(__fsub_rn(z2, mn), c2);
        float c3 = __fmul_rn(__fsub_rn(z3, mn), c2);
        int i0 = min(max((int)c0, 0), NB_BINS - 1);
        int i1 = min(max((int)c1, 0), NB_BINS - 1);
        int i2 = min(max((int)cc, 0), NB_BINS - 1);
        int i3 = min(max((int)c3, 0), NB_BINS - 1);
        atomicAdd(&hist[i0], 1u);
        atomicAdd(&hist[i1], 1u);
        atomicAdd(&hist[i2], 1u);
        atomicAdd(&hist[i3], 1u);
    }
    __syncthreads();

    // ---------------- softmax over counts (R11 two-pass) ----------------
    unsigned cm = 0u;
    #pragma unroll
    for (int i = 0; i < NB_BINS / 1024; ++i) cm = max(cm, hist[t + i * 1024]);
    #pragma unroll
    for (int o = 16; o; o >>= 1) cm = max(cm, __shfl_down_sync(0xffffffffu, cm, o));
    if (lane == 0) s_red[wid] = (float)cm;
    __syncthreads();
    if (wid == 0) {
        float v = s_red[lane];
        #pragma unroll
        for (int o = 16; o; o >>= 1) v = fmaxf(v, __shfl_down_sync(0xffffffffu, v, o));
        if (lane == 0) s_bcast[2] = v;
    }
    __syncthreads();
    const int cmaxi = (int)s_bcast[2];

    // sum of exp(count - cmax) via LUT (bit-identical to expf on int args)
    float sum = 0.0f;
    #pragma unroll
    for (int i = 0; i < NB_BINS / 1024; ++i) {
        int dd = cmaxi - (int)hist[t + i * 1024];
        sum += (dd < 256) ? s_lut[dd] : 0.0f;
    }
    #pragma unroll
    for (int o = 16; o; o >>= 1) sum += __shfl_down_sync(0xffffffffu, sum, o);
    if (lane == 0) s_red[wid] = sum;
    __syncthreads();
    if (wid == 0) {
        float v = s_red[lane];
        #pragma unroll
        for (int o = 16; o; o >>= 1) v += __shfl_down_sync(0xffffffffu, v, o);
        if (lane == 0) s_bcast[3] = v;
    }
    __syncthreads();
    const float rtot = __fdiv_rn(1.0f, s_bcast[3]);

    // epilogue: probs = exp(c-cmax)/total; prune < 1e-10; out = (x*p)*128
    float* orow = out + (size_t)b * NB_BINS;
    #pragma unroll
    for (int i = 0; i < NB_BINS / 1024; ++i) {
        int n = t + i * 1024;
        int dd = cmaxi - (int)hist[n];
        float ev = (dd < 256) ? s_lut[dd] : 0.0f;
        float p = __fmul_rn(ev, rtot);
        if (p < 1e-10f) p = 0.0f;
        orow[n] = __fmul_rn(__fmul_rn(xv[i], p), 128.0f);
    }
}

extern "C" void kernel_launch(void* const* d_in, const int* in_sizes, int n_in,
                              void* d_out, int out_size) {
    const float* zm  = (const float*)d_in[0];
    const float* zv  = (const float*)d_in[1];
    const float* x   = (const float*)d_in[2];
    const float* eps = (const float*)d_in[3];
    float* out = (float*)d_out;

    const int smem = NB_BINS * 4 + 2 * NB_DIM * 4;  // 73728 B
    cudaFuncSetAttribute(k_fused, cudaFuncAttributeMaxDynamicSharedMemorySize, smem);

    k_fused<<<NB_B, 1024, smem>>>(zm, zv, eps, x, out);
}

// round 15
// speedup vs baseline: 1.5508x; 1.0111x over previous
#include <cuda_runtime.h>
#include <cuda_bf16.h>
#include <stdint.h>

#define NB_B     128      // batch rows
#define NB_DIM   1024     // latent dim
#define NB_BINS  16384    // histogram bins / num_outputs
#define NB_MULT  128      // multiplier

// Bit-exact replica of XLA CPU's vectorized f32 exp (GenerateVF32Exp,
// Cephes polynomial).  DO NOT MODIFY — bit-exactness verified R9.
__device__ __forceinline__ float xla_expf(float input) {
    float x = fminf(fmaxf(input, -88.3762626647949f), 88.3762626647950f);
    float fx = floorf(fmaf(x, 1.44269504088896341f, 0.5f));
    float tmp = __fmul_rn(fx, 0.693359375f);
    float zz  = __fmul_rn(fx, -2.12194440e-4f);
    x = __fsub_rn(x, tmp);
    x = __fsub_rn(x, zz);
    zz = __fmul_rn(x, x);
    float y = fmaf(x, 1.9875691500E-4f, 1.3981999507E-3f);
    y = fmaf(y, x, 8.3334519073E-3f);
    y = fmaf(y, x, 4.1665795894E-2f);
    y = fmaf(y, x, 1.6666665459E-1f);
    y = fmaf(y, x, 5.0000001201E-1f);
    y = fmaf(y, zz, x);
    y = __fadd_rn(1.0f, y);
    int emm0 = ((int)fx + 127) << 23;
    float two_n = __int_as_float(emm0);
    return fmaxf(__fmul_rn(y, two_n), input);
}

// ---------------- Fused kernel: one CTA per batch row ----------------
// Phase A: stream row slice (512KB), per-thread RAW-eps extrema (z extrema
//          derived exactly via monotonicity), block reduce.
// Phase B: re-stream slice (L2-resident); DUAL smem sub-histograms (warps
//          0-15 -> hist0, 16-31 -> hist1) to halve atomic conflict degree.
// Tail:    merge sub-hists (exclusive bin ownership, no extra sync), then
//          two-pass softmax over integer counts via exp LUT.
__global__ __launch_bounds__(1024) void k_fused(const float* __restrict__ zm,
                                                const float* __restrict__ zv,
                                                const float* __restrict__ eps,
                                                const float* __restrict__ x,
                                                float* __restrict__ out) {
    extern __shared__ unsigned smem[];
    unsigned* hist  = smem;                         // NB_BINS u32 (64KB)
    unsigned* hist1 = smem + NB_BINS;               // NB_BINS u32 (64KB)
    float* s_s  = (float*)(smem + 2 * NB_BINS);     // NB_DIM
    float* s_zm = s_s + NB_DIM;                     // NB_DIM
    __shared__ float s_rmin[32], s_rmax[32], s_red[32];
    __shared__ float s_bcast[4];
    __shared__ float s_lut[256];                    // expf(-d), d=0..255

    const int b = blockIdx.x;
    const int t = threadIdx.x;
    const int wid = t >> 5, lane = t & 31;

    // ---- prefetch x row (consumed only in epilogue; hides under phase A) ----
    float xv[NB_BINS / 1024];
    {
        const float* xrow = x + (size_t)b * NB_BINS;
        #pragma unroll
        for (int i = 0; i < NB_BINS / 1024; ++i) xv[i] = __ldg(&xrow[t + i * 1024]);
    }

    // zero both histograms (128KB) with 16B stores
    {
        uint4* h4 = (uint4*)smem;
        uint4 z4 = make_uint4(0u, 0u, 0u, 0u);
        #pragma unroll
        for (int i = 0; i < (2 * NB_BINS / 4) / 1024; ++i) h4[t + i * 1024] = z4;
    }

    // exp LUT: expf(-(float)d) — bit-identical to the softmax expf calls
    // (integer args). expf(x)==0 exactly for x <= -104, so d>=256 -> 0.
    if (t < 256) s_lut[t] = expf(-(float)t);

    // Cache z_mean row and stdev row.  0.5*zv is exact (power of 2).
    s_zm[t] = zm[b * NB_DIM + t];
    s_s[t]  = xla_expf(__fmul_rn(0.5f, zv[b * NB_DIM + t]));
    __syncthreads();

    const int jrow = t >> 8;      // 0..3
    const int d4   = t & 255;     // 0..255
    const int d    = d4 * 4;

    const float* __restrict__ row_base = eps + (size_t)b * NB_MULT * NB_DIM;

    // ---------------- Phase A: raw-eps per-column extrema ----------------
    float m0 =  3.402823466e38f, m1 = m0, m2 = m0, m3 = m0;
    float M0 = -3.402823466e38f, M1 = M0, M2 = M0, M3 = M0;

    #pragma unroll 4
    for (int it = 0; it < 32; ++it) {
        int j = it * 4 + jrow;
        const float4* ep = reinterpret_cast<const float4*>(row_base + (size_t)j * NB_DIM);
        float4 e = ep[d4];
        m0 = fminf(m0, e.x); M0 = fmaxf(M0, e.x);
        m1 = fminf(m1, e.y); M1 = fmaxf(M1, e.y);
        m2 = fminf(m2, e.z); M2 = fmaxf(M2, e.z);
        m3 = fminf(m3, e.w); M3 = fmaxf(M3, e.w);
    }

    const float sm0 = s_zm[d], sm1 = s_zm[d+1], sm2 = s_zm[d+2], sm3 = s_zm[d+3];
    const float ss0 = s_s[d],  ss1 = s_s[d+1],  ss2 = s_s[d+2],  ss3 = s_s[d+3];

    // Transform raw extrema -> z extrema (exact by monotonicity; ss>0).
    // z = zm + s*eps, NON-contracted (plain fmul/fadd). DO NOT fuse.
    float vmin, vmax;
    {
        float l0 = __fadd_rn(sm0, __fmul_rn(ss0, m0));
        float l1 = __fadd_rn(sm1, __fmul_rn(ss1, m1));
        float l2 = __fadd_rn(sm2, __fmul_rn(ss2, m2));
        float l3 = __fadd_rn(sm3, __fmul_rn(ss3, m3));
        float h0 = __fadd_rn(sm0, __fmul_rn(ss0, M0));
        float h1 = __fadd_rn(sm1, __fmul_rn(ss1, M1));
        float h2 = __fadd_rn(sm2, __fmul_rn(ss2, M2));
        float h3 = __fadd_rn(sm3, __fmul_rn(ss3, M3));
        vmin = fminf(fminf(l0, l1), fminf(l2, l3));
        vmax = fmaxf(fmaxf(h0, h1), fmaxf(h2, h3));
    }

    #pragma unroll
    for (int o = 16; o; o >>= 1) {
        vmin = fminf(vmin, __shfl_down_sync(0xffffffffu, vmin, o));
        vmax = fmaxf(vmax, __shfl_down_sync(0xffffffffu, vmax, o));
    }
    if (lane == 0) { s_rmin[wid] = vmin; s_rmax[wid] = vmax; }
    __syncthreads();
    if (wid == 0) {
        vmin = s_rmin[lane];
        vmax = s_rmax[lane];
        #pragma unroll
        for (int o = 16; o; o >>= 1) {
            vmin = fminf(vmin, __shfl_down_sync(0xffffffffu, vmin, o));
            vmax = fmaxf(vmax, __shfl_down_sync(0xffffffffu, vmax, o));
        }
        if (lane == 0) { s_bcast[0] = vmin; s_bcast[1] = vmax; }
    }
    __syncthreads();

    const float mn = s_bcast[0];
    const float dr = __fsub_rn(s_bcast[1], mn);
    // Fast-math reciprocal fold: scaled = (z-mn) * c2, c2 = (1/dr)*16384
    // (*2^14 exact; rnd(16384/dr) == rnd(1/dr)*2^14 bitwise). DO NOT change.
    const float c2 = __fmul_rn(__fdiv_rn(1.0f, dr), 16384.0f);

    // ---------------- Phase B: histogram (L2-hot re-read) ----------------
    // Warps 0-15 -> hist, warps 16-31 -> hist1 (halves conflict degree).
    unsigned* myhist = (wid < 16) ? hist : hist1;
    #pragma unroll 8
    for (int it = 0; it < 32; ++it) {
        int j = it * 4 + jrow;
        const float4* ep = reinterpret_cast<const float4*>(row_base + (size_t)j * NB_DIM);
        float4 e = ep[d4];
        float z0 = __fadd_rn(sm0, __fmul_rn(ss0, e.x));
        float z1 = __fadd_rn(sm1, __fmul_rn(ss1, e.y));
        float z2 = __fadd_rn(sm2, __fmul_rn(ss2, e.z));
        float z3 = __fadd_rn(sm3, __fmul_rn(ss3, e.w));
        float c0 = __fmul_rn(__fsub_rn(z0, mn), c2);
        float c1 = __fmul_rn(__fsub_rn(z1, mn), c2);
        float cc = __fmul_rn(__fsub_rn(z2, mn), c2);
        float c3 = __fmul_rn(__fsub_rn(z3, mn), c2);
        int i0 = min(max((int)c0, 0), NB_BINS - 1);
        int i1 = min(max((int)c1, 0), NB_BINS - 1);
        int i2 = min(max((int)cc, 0), NB_BINS - 1);
        int i3 = min(max((int)c3, 0), NB_BINS - 1);
        atomicAdd(&myhist[i0], 1u);
        atomicAdd(&myhist[i1], 1u);
        atomicAdd(&myhist[i2], 1u);
        atomicAdd(&myhist[i3], 1u);
    }
    __syncthreads();

    // ---------------- softmax over counts (two-pass, LUT) ----------------
    // Merge sub-hists in the max pass: bins t+i*1024 are owned exclusively
    // by thread t across all tail loops, so the merge write needs no sync.
    unsigned cm = 0u;
    #pragma unroll
    for (int i = 0; i < NB_BINS / 1024; ++i) {
        int n = t + i * 1024;
        unsigned c = hist[n] + hist1[n];
        hist[n] = c;
        cm = max(cm, c);
    }
    #pragma unroll
    for (int o = 16; o; o >>= 1) cm = max(cm, __shfl_down_sync(0xffffffffu, cm, o));
    if (lane == 0) s_red[wid] = (float)cm;
    __syncthreads();
    if (wid == 0) {
        float v = s_red[lane];
        #pragma unroll
        for (int o = 16; o; o >>= 1) v = fmaxf(v, __shfl_down_sync(0xffffffffu, v, o));
        if (lane == 0) s_bcast[2] = v;
    }
    __syncthreads();
    const int cmaxi = (int)s_bcast[2];

    // sum of exp(count - cmax) via LUT (bit-identical to expf on int args)
    float sum = 0.0f;
    #pragma unroll
    for (int i = 0; i < NB_BINS / 1024; ++i) {
        int dd = cmaxi - (int)hist[t + i * 1024];
        sum += (dd < 256) ? s_lut[dd] : 0.0f;
    }
    #pragma unroll
    for (int o = 16; o; o >>= 1) sum += __shfl_down_sync(0xffffffffu, sum, o);
    if (lane == 0) s_red[wid] = sum;
    __syncthreads();
    if (wid == 0) {
        float v = s_red[lane];
        #pragma unroll
        for (int o = 16; o; o >>= 1) v += __shfl_down_sync(0xffffffffu, v, o);
        if (lane == 0) s_bcast[3] = v;
    }
    __syncthreads();
    const float rtot = __fdiv_rn(1.0f, s_bcast[3]);

    // epilogue: probs = exp(c-cmax)/total; prune < 1e-10; out = (x*p)*128
    float* orow = out + (size_t)b * NB_BINS;
    #pragma unroll
    for (int i = 0; i < NB_BINS / 1024; ++i) {
        int n = t + i * 1024;
        int dd = cmaxi - (int)hist[n];
        float ev = (dd < 256) ? s_lut[dd] : 0.0f;
        float p = __fmul_rn(ev, rtot);
        if (p < 1e-10f) p = 0.0f;
        orow[n] = __fmul_rn(__fmul_rn(xv[i], p), 128.0f);
    }
}

extern "C" void kernel_launch(void* const* d_in, const int* in_sizes, int n_in,
                              void* d_out, int out_size) {
    const float* zm  = (const float*)d_in[0];
    const float* zv  = (const float*)d_in[1];
    const float* x   = (const float*)d_in[2];
    const float* eps = (const float*)d_in[3];
    float* out = (float*)d_out;

    const int smem = 2 * NB_BINS * 4 + 2 * NB_DIM * 4;  // 139264 B
    cudaFuncSetAttribute(k_fused, cudaFuncAttributeMaxDynamicSharedMemorySize, smem);

    k_fused<<<NB_B, 1024, smem>>>(zm, zv, eps, x, out);
}